// round 13
// baseline (speedup 1.0000x reference)
#include <cuda_runtime.h>

#define B 8
#define M 8192
#define N 8192
#define SPLITS 64
#define ROWS (M / SPLITS)            // 128 rows per split
#define TPB 128
#define COLS_PER_BLOCK (TPB * 4)     // 512 columns per block (4 floats per thread)
#define NBLK (N / COLS_PER_BLOCK)    // 16 -> grid 16x64 = 1024 blocks
#define GRID (NBLK * SPLITS)         // 1024 co-resident blocks (<= 152*7)

// Split-K partial sums: [SPLITS][B][N] floats = 16 MB device scratch (L2-hot).
__device__ float g_part[(size_t)SPLITS * B * N];

// Single-wave global barrier state. Graph-replay-safe: g_arrive returns to 0
// every launch; g_phase alternates 0/1/0/1 across launches.
__device__ unsigned g_arrive = 0;
__device__ unsigned g_phase  = 0;

// Packed fp32x2 FMA: d = a*b + d  (sm_103a FFMA2, only reachable via PTX)
#define FMA2(d, a, b) \
    asm("fma.rn.f32x2 %0, %1, %2, %0;" : "+l"(d) : "l"(a), "l"(b))

__global__ void __launch_bounds__(TPB, 7)
snn_fused(const float* __restrict__ pre,   // [B][M]
          const float* __restrict__ W,     // [M][N] row-major
          const float* __restrict__ thr,   // [B][N]
          const float* __restrict__ cst,   // [B][N]
          float* __restrict__ out)         // [B][N]
{
    __shared__ unsigned long long pre_s2[ROWS][B];

    const int nb  = blockIdx.x;
    const int s   = blockIdx.y;
    const int tid = threadIdx.x;
    const int m0  = s * ROWS;

    // Read barrier phase BEFORE any work: every block starts (single wave)
    // before the 1024th arrival can flip it.
    const unsigned myphase = *((volatile unsigned*)&g_phase);

    // ---- Phase 1: split-K GEMV (round-10 geometry, unchanged) ----
    #pragma unroll
    for (int b = 0; b < B; b++) {
        float p = pre[b * M + m0 + tid];
        float2 pp = make_float2(p, p);
        pre_s2[tid][b] = *reinterpret_cast<unsigned long long*>(&pp);
    }
    __syncthreads();

    const int n0 = nb * COLS_PER_BLOCK + tid * 4;
    const float4* Wp = reinterpret_cast<const float4*>(W + (size_t)m0 * N + n0);
    const size_t S4 = N / 4;

    unsigned long long acc[B][2];
    #pragma unroll
    for (int b = 0; b < B; b++) { acc[b][0] = 0ull; acc[b][1] = 0ull; }

    #define DO_ROW(WV, MI) do {                                              \
        ulonglong2 wv = *reinterpret_cast<ulonglong2*>(&(WV));               \
        const ulonglong2* ps =                                               \
            reinterpret_cast<const ulonglong2*>(&pre_s2[(MI)][0]);           \
        ulonglong2 pa = ps[0];                                               \
        ulonglong2 pb = ps[1];                                               \
        ulonglong2 pc = ps[2];                                               \
        ulonglong2 pd = ps[3];                                               \
        FMA2(acc[0][0], wv.x, pa.x); FMA2(acc[0][1], wv.y, pa.x);            \
        FMA2(acc[1][0], wv.x, pa.y); FMA2(acc[1][1], wv.y, pa.y);            \
        FMA2(acc[2][0], wv.x, pb.x); FMA2(acc[2][1], wv.y, pb.x);            \
        FMA2(acc[3][0], wv.x, pb.y); FMA2(acc[3][1], wv.y, pb.y);            \
        FMA2(acc[4][0], wv.x, pc.x); FMA2(acc[4][1], wv.y, pc.x);            \
        FMA2(acc[5][0], wv.x, pc.y); FMA2(acc[5][1], wv.y, pc.y);            \
        FMA2(acc[6][0], wv.x, pd.x); FMA2(acc[6][1], wv.y, pd.x);            \
        FMA2(acc[7][0], wv.x, pd.y); FMA2(acc[7][1], wv.y, pd.y);            \
    } while (0)

    #pragma unroll 1
    for (int m = 0; m < ROWS; m += 4) {
        float4 w0 = __ldcs(Wp + (size_t)(m + 0) * S4);
        float4 w1 = __ldcs(Wp + (size_t)(m + 1) * S4);
        float4 w2 = __ldcs(Wp + (size_t)(m + 2) * S4);
        float4 w3 = __ldcs(Wp + (size_t)(m + 3) * S4);
        DO_ROW(w0, m + 0);
        DO_ROW(w1, m + 1);
        DO_ROW(w2, m + 2);
        DO_ROW(w3, m + 3);
    }
    #undef DO_ROW

    // Partials -> L2 (stcg: no L1 residence, globally visible).
    #pragma unroll
    for (int b = 0; b < B; b++) {
        float2 lo = *reinterpret_cast<float2*>(&acc[b][0]);
        float2 hi = *reinterpret_cast<float2*>(&acc[b][1]);
        float4 v = make_float4(lo.x, lo.y, hi.x, hi.y);
        __stcg(reinterpret_cast<float4*>(
                   &g_part[((size_t)s * B + b) * N + n0]), v);
    }

    // ---- Global barrier (all 1024 blocks co-resident) ----
    __threadfence();          // this thread's partial stores visible device-wide
    __syncthreads();          // whole block's stores + fences done
    if (tid == 0) {
        unsigned old = atomicAdd(&g_arrive, 1u);
        if (old == GRID - 1) {            // last arriver: reset + release
            g_arrive = 0;
            __threadfence();
            atomicExch(&g_phase, myphase ^ 1u);
        }
        volatile unsigned* ph = &g_phase;
        while (*ph == myphase) { __nanosleep(64); }
    }
    __syncthreads();
    __threadfence();          // acquire: partials of all blocks now readable

    // ---- Phase 2: cooperative reduce. 2 threads per output, 32 splits each.
    const int bid  = s * NBLK + nb;                 // 0..1023
    const int o    = bid * 64 + (tid >> 1);         // output index in [B*N]
    const int k    = tid & 1;                       // split half
    const size_t plane = (size_t)B * N;
    const float* p = &g_part[(size_t)(k * 32) * plane + o];

    float sum = 0.f;
    #pragma unroll 1
    for (int i = 0; i < 32; i += 8) {
        const float* q = p + (size_t)i * plane;
        float v0 = __ldcg(q + 0 * plane);
        float v1 = __ldcg(q + 1 * plane);
        float v2 = __ldcg(q + 2 * plane);
        float v3 = __ldcg(q + 3 * plane);
        float v4 = __ldcg(q + 4 * plane);
        float v5 = __ldcg(q + 5 * plane);
        float v6 = __ldcg(q + 6 * plane);
        float v7 = __ldcg(q + 7 * plane);
        sum += ((v0 + v1) + (v2 + v3)) + ((v4 + v5) + (v6 + v7));
    }

    const float full = sum + __shfl_xor_sync(0xffffffffu, sum, 1);
    if (k == 0) {
        float o_val = full + cst[o] - thr[o];
        out[o] = fminf(fmaxf(o_val, 0.f), 0.9f);
    }
}

extern "C" void kernel_launch(void* const* d_in, const int* in_sizes, int n_in,
                              void* d_out, int out_size)
{
    const float* pre = (const float*)d_in[0];   // pre_spikes [8,1,8192]
    const float* W   = (const float*)d_in[1];   // W [8192,8192]
    const float* thr = (const float*)d_in[2];   // thr [8,1,8192]
    const float* cst = (const float*)d_in[3];   // const_inp [8,1,8192]
    float* out = (float*)d_out;                 // [8,1,8192]

    dim3 grid(NBLK, SPLITS);                    // 16 x 64 = 1024 blocks
    snn_fused<<<grid, TPB>>>(pre, W, thr, cst, out);
}

// round 14
// speedup vs baseline: 1.0056x; 1.0056x over previous
#include <cuda_runtime.h>
#include <cstdint>

#define B 8
#define M 8192
#define N 8192
#define SPLITS 64
#define ROWS (M / SPLITS)            // 128 rows per split
#define TPB 128
#define COLS_PER_BLOCK (TPB * 4)     // 512 columns per block (4 floats per thread)
#define NBLK (N / COLS_PER_BLOCK)    // 16 -> grid 16x64 = 1024 blocks

// Split-K partial sums: [SPLITS][B][N] floats = 16 MB device scratch.
__device__ float g_part[(size_t)SPLITS * B * N];

// Packed fp32x2 FMA: d = a*b + d  (sm_103a FFMA2, only reachable via PTX)
#define FMA2(d, a, b) \
    asm("fma.rn.f32x2 %0, %1, %2, %0;" : "+l"(d) : "l"(a), "l"(b))

__global__ void __launch_bounds__(TPB, 7)
snn_gemv_split(const float* __restrict__ pre,   // [B][M]
               const float* __restrict__ W)     // [M][N] row-major
{
    // Pre-spikes pre-duplicated: pre_s2[r][b] = {p, p} (64-bit), so packed
    // multipliers come straight from LDS.128. 128*8*8 = 8 KB smem.
    __shared__ unsigned long long pre_s2[ROWS][B];

    const int nb  = blockIdx.x;
    const int s   = blockIdx.y;
    const int tid = threadIdx.x;
    const int m0  = s * ROWS;

    // tid == row (ROWS == TPB == 128)
    #pragma unroll
    for (int b = 0; b < B; b++) {
        float p = pre[b * M + m0 + tid];
        float2 pp = make_float2(p, p);
        pre_s2[tid][b] = *reinterpret_cast<unsigned long long*>(&pp);
    }
    __syncthreads();

    const int n0 = nb * COLS_PER_BLOCK + tid * 4;
    const float4* Wp = reinterpret_cast<const float4*>(W + (size_t)m0 * N + n0);
    const size_t S4 = N / 4;         // row stride in float4 (16 B) units

    // acc[b][0] = packed cols {0,1}, acc[b][1] = packed cols {2,3}
    unsigned long long acc[B][2];
    #pragma unroll
    for (int b = 0; b < B; b++) { acc[b][0] = 0ull; acc[b][1] = 0ull; }

    #define DO_ROW(WV, MI) do {                                              \
        ulonglong2 wv = *reinterpret_cast<ulonglong2*>(&(WV));               \
        const ulonglong2* ps =                                               \
            reinterpret_cast<const ulonglong2*>(&pre_s2[(MI)][0]);           \
        ulonglong2 pa = ps[0];                                               \
        ulonglong2 pb = ps[1];                                               \
        ulonglong2 pc = ps[2];                                               \
        ulonglong2 pd = ps[3];                                               \
        FMA2(acc[0][0], wv.x, pa.x); FMA2(acc[0][1], wv.y, pa.x);            \
        FMA2(acc[1][0], wv.x, pa.y); FMA2(acc[1][1], wv.y, pa.y);            \
        FMA2(acc[2][0], wv.x, pb.x); FMA2(acc[2][1], wv.y, pb.x);            \
        FMA2(acc[3][0], wv.x, pb.y); FMA2(acc[3][1], wv.y, pb.y);            \
        FMA2(acc[4][0], wv.x, pc.x); FMA2(acc[4][1], wv.y, pc.x);            \
        FMA2(acc[5][0], wv.x, pc.y); FMA2(acc[5][1], wv.y, pc.y);            \
        FMA2(acc[6][0], wv.x, pd.x); FMA2(acc[6][1], wv.y, pd.x);            \
        FMA2(acc[7][0], wv.x, pd.y); FMA2(acc[7][1], wv.y, pd.y);            \
    } while (0)

    // Explicit 4-deep load batching, .CS so the one-shot W stream streams
    // through L2 without evicting the partial buffer.
    #pragma unroll 1
    for (int m = 0; m < ROWS; m += 4) {
        float4 w0 = __ldcs(Wp + (size_t)(m + 0) * S4);
        float4 w1 = __ldcs(Wp + (size_t)(m + 1) * S4);
        float4 w2 = __ldcs(Wp + (size_t)(m + 2) * S4);
        float4 w3 = __ldcs(Wp + (size_t)(m + 3) * S4);
        DO_ROW(w0, m + 0);
        DO_ROW(w1, m + 1);
        DO_ROW(w2, m + 2);
        DO_ROW(w3, m + 3);
    }
    #undef DO_ROW

    #pragma unroll
    for (int b = 0; b < B; b++) {
        float2 lo = *reinterpret_cast<float2*>(&acc[b][0]);
        float2 hi = *reinterpret_cast<float2*>(&acc[b][1]);
        float4 v = make_float4(lo.x, lo.y, hi.x, hi.y);
        *reinterpret_cast<float4*>(&g_part[((size_t)s * B + b) * N + n0]) = v;
    }
}

// ---------------------------------------------------------------------------
// Reduce via cp.async.bulk: one thread issues 64 bulk copies (512 B each,
// one per split plane) into smem; mbarrier tracks completion by bytes.
// No destination registers -> full 32 KB per block in flight.
// ---------------------------------------------------------------------------
#define RED_TPB 128
#define RED_BLOCKS ((B * N) / RED_TPB)   // 512 blocks
#define TILE_BYTES (SPLITS * RED_TPB * 4)   // 32 KB

__device__ __forceinline__ uint32_t smem_u32(const void* p) {
    uint32_t a;
    asm("{ .reg .u64 t; cvta.to.shared.u64 t, %1; cvt.u32.u64 %0, t; }"
        : "=r"(a) : "l"(p));
    return a;
}

__global__ void __launch_bounds__(RED_TPB)
snn_reduce(const float* __restrict__ thr,       // [B][N]
           const float* __restrict__ cst,       // [B][N]
           float* __restrict__ out)             // [B][N]
{
    __shared__ __align__(16) float tile[SPLITS][RED_TPB];   // 32 KB
    __shared__ __align__(8) unsigned long long mbar;

    const int t    = threadIdx.x;
    const int idx0 = blockIdx.x * RED_TPB;
    const uint32_t mbar_a = smem_u32(&mbar);

    if (t == 0) {
        asm volatile("mbarrier.init.shared.b64 [%0], 1;"
                     :: "r"(mbar_a) : "memory");
    }
    __syncthreads();

    if (t == 0) {
        asm volatile("mbarrier.arrive.expect_tx.shared.b64 _, [%0], %1;"
                     :: "r"(mbar_a), "r"((uint32_t)TILE_BYTES) : "memory");
        #pragma unroll 1
        for (int s = 0; s < SPLITS; s++) {
            uint32_t dst = smem_u32(&tile[s][0]);
            const float* src = &g_part[(size_t)s * B * N + idx0];
            asm volatile(
                "cp.async.bulk.shared::cta.global.mbarrier::complete_tx::bytes "
                "[%0], [%1], %2, [%3];"
                :: "r"(dst), "l"(src), "r"((uint32_t)(RED_TPB * 4)), "r"(mbar_a)
                : "memory");
        }
    }

    // Overlap the bulk-copy wait with the const/threshold loads.
    const float c  = cst[idx0 + t];
    const float th = thr[idx0 + t];

    // Wait parity 0 (barrier freshly initialized each launch).
    {
        uint32_t done;
        asm volatile(
            "{\n\t"
            ".reg .pred p;\n\t"
            "mbarrier.try_wait.parity.acquire.cta.shared::cta.b64 p, [%1], %2;\n\t"
            "selp.b32 %0, 1, 0, p;\n\t"
            "}"
            : "=r"(done) : "r"(mbar_a), "r"(0u) : "memory");
        while (!done) {
            asm volatile(
                "{\n\t"
                ".reg .pred p;\n\t"
                "mbarrier.try_wait.parity.acquire.cta.shared::cta.b64 p, [%1], %2, 0x989680;\n\t"
                "selp.b32 %0, 1, 0, p;\n\t"
                "}"
                : "=r"(done) : "r"(mbar_a), "r"(0u) : "memory");
        }
    }

    // Column-per-thread sum: warp reads 32 consecutive floats per plane ->
    // conflict-free LDS, 64 pipelined smem loads.
    float sum = 0.f;
    #pragma unroll
    for (int s = 0; s < SPLITS; s++)
        sum += tile[s][t];

    float o = sum + c - th;
    out[idx0 + t] = fminf(fmaxf(o, 0.f), 0.9f);
}

extern "C" void kernel_launch(void* const* d_in, const int* in_sizes, int n_in,
                              void* d_out, int out_size)
{
    const float* pre = (const float*)d_in[0];   // pre_spikes [8,1,8192]
    const float* W   = (const float*)d_in[1];   // W [8192,8192]
    const float* thr = (const float*)d_in[2];   // thr [8,1,8192]
    const float* cst = (const float*)d_in[3];   // const_inp [8,1,8192]
    float* out = (float*)d_out;                 // [8,1,8192]

    dim3 grid(NBLK, SPLITS);                    // 16 x 64 = 1024 blocks
    snn_gemv_split<<<grid, TPB>>>(pre, W);

    snn_reduce<<<RED_BLOCKS, RED_TPB>>>(thr, cst, out);
}